// round 9
// baseline (speedup 1.0000x reference)
// R9 resubmission of the fp16-split tensor-core design (R8 hit broker infra flake).
#include <cuda_runtime.h>
#include <cuda_fp16.h>
#include <math.h>
#include <stdint.h>

#define NN_NODES 100000
#define NN_EDGES 1600000
#define NRELS 4
#define DIMV 64
#define EPSV 1e-10f
#define NSEG (NN_NODES * NRELS)          // 400000
#define SCAN_CHUNK 2048
#define NB1 ((NSEG + SCAN_CHUNK - 1) / SCAN_CHUNK)   // 196

#define H_LDA 328     // halfs per row, hidden staging (K=320 + 8 pad)
#define H_K   320
#define W_LDA 136     // halfs per row, highway staging (K=128 + 8 pad)

// ---------------- scratch (static device allocations) ----------------
__device__ int    g_cnt[NSEG];
__device__ int    g_off[NSEG];
__device__ int    g_pos[NSEG];
__device__ int    g_bsum[256];
__device__ int    g_bscan[256];
__device__ float2 g_pack[NN_EDGES];                      // {.x = src bits, .y = weight}
__device__ float  g_upd[(size_t)NSEG * DIMV];            // 102.4 MB (normalized upd)
__device__ float  g_buf[3][(size_t)NN_NODES * DIMV];     // hid0, hid1, gated

__device__ __forceinline__ float sigf(float v) {
    return 1.0f / (1.0f + expf(-v));
}

// fp16 two-term split of a float pair
__device__ __forceinline__ void split2(float a, float b, __half2& hi, __half2& lo) {
    __half h0 = __float2half_rn(a), h1 = __float2half_rn(b);
    hi = __halves2half2(h0, h1);
    lo = __halves2half2(__float2half_rn(a - __half2float(h0)),
                        __float2half_rn(b - __half2float(h1)));
}

// m16n8k16 f16 mma, f32 accum
__device__ __forceinline__ void mma_f16(float* d, const uint32_t* a, uint32_t b0, uint32_t b1) {
    asm volatile(
        "mma.sync.aligned.m16n8k16.row.col.f32.f16.f16.f32 "
        "{%0,%1,%2,%3}, {%4,%5,%6,%7}, {%8,%9}, {%0,%1,%2,%3};"
        : "+f"(d[0]), "+f"(d[1]), "+f"(d[2]), "+f"(d[3])
        : "r"(a[0]), "r"(a[1]), "r"(a[2]), "r"(a[3]), "r"(b0), "r"(b1));
}

__device__ __forceinline__ uint32_t ldsm_u32(const __half* p) {
    return *(const uint32_t*)p;
}

// ---------------- CSR build (once per launch) ----------------
__global__ void zero_kernel() {
    int i = blockIdx.x * blockDim.x + threadIdx.x;
    if (i < NSEG) { g_cnt[i] = 0; g_pos[i] = 0; }
}

__global__ void hist_kernel(const int* __restrict__ dst, const int* __restrict__ rel) {
    int e = blockIdx.x * blockDim.x + threadIdx.x;
    if (e < NN_EDGES)
        atomicAdd(&g_cnt[dst[e] * NRELS + rel[e]], 1);
}

__global__ __launch_bounds__(1024) void scanA_kernel() {
    __shared__ int sm[1024];
    int b = blockIdx.x, t = threadIdx.x;
    int i0 = b * SCAN_CHUNK + t * 2;
    int a0 = (i0     < NSEG) ? g_cnt[i0]     : 0;
    int a1 = (i0 + 1 < NSEG) ? g_cnt[i0 + 1] : 0;
    int tsum = a0 + a1;
    sm[t] = tsum;
    __syncthreads();
    for (int off = 1; off < 1024; off <<= 1) {
        int v = (t >= off) ? sm[t - off] : 0;
        __syncthreads();
        sm[t] += v;
        __syncthreads();
    }
    int excl = sm[t] - tsum;
    if (i0     < NSEG) g_off[i0]     = excl;
    if (i0 + 1 < NSEG) g_off[i0 + 1] = excl + a0;
    if (t == 1023) g_bsum[b] = sm[1023];
}

__global__ __launch_bounds__(256) void scanB_kernel() {
    __shared__ int sm[256];
    int t = threadIdx.x;
    int v = (t < NB1) ? g_bsum[t] : 0;
    sm[t] = v;
    __syncthreads();
    for (int off = 1; off < 256; off <<= 1) {
        int u = (t >= off) ? sm[t - off] : 0;
        __syncthreads();
        sm[t] += u;
        __syncthreads();
    }
    g_bscan[t] = sm[t] - v;   // exclusive
}

__global__ void fill_kernel(const float* __restrict__ ew,
                            const int* __restrict__ src,
                            const int* __restrict__ dst,
                            const int* __restrict__ rel) {
    int e = blockIdx.x * blockDim.x + threadIdx.x;
    if (e >= NN_EDGES) return;
    int seg = dst[e] * NRELS + rel[e];
    int p = atomicAdd(&g_pos[seg], 1);
    int idx = g_off[seg] + g_bscan[seg >> 11] + p;
    g_pack[idx] = make_float2(__int_as_float(src[e]), ew[e]);
}

// ---------------- gather: upd[seg] = (sum_e x[src]*w) / (sum_e w + eps) ----------
__global__ __launch_bounds__(256) void gather_kernel(const float* __restrict__ x) {
    unsigned t = blockIdx.x * blockDim.x + threadIdx.x;
    unsigned seg = t >> 4;
    if (seg >= NSEG) return;
    int c = (t & 15) << 2;
    int st = g_off[seg] + g_bscan[seg >> 11];
    int cnt = g_cnt[seg];
    int en = st + cnt;
    float4 acc = make_float4(0.f, 0.f, 0.f, 0.f);
    float ws = 0.f;
    int i = st;
    int en4 = st + (cnt & ~3);
    while (i < en4) {
        float2 p0 = __ldg(&g_pack[i]);
        float2 p1 = __ldg(&g_pack[i + 1]);
        float2 p2 = __ldg(&g_pack[i + 2]);
        float2 p3 = __ldg(&g_pack[i + 3]);
        int s0 = __float_as_int(p0.x);
        int s1 = __float_as_int(p1.x);
        int s2 = __float_as_int(p2.x);
        int s3 = __float_as_int(p3.x);
        float4 v0 = *(const float4*)(x + (size_t)s0 * DIMV + c);
        float4 v1 = *(const float4*)(x + (size_t)s1 * DIMV + c);
        float4 v2 = *(const float4*)(x + (size_t)s2 * DIMV + c);
        float4 v3 = *(const float4*)(x + (size_t)s3 * DIMV + c);
        acc.x += v0.x * p0.y + v1.x * p1.y + v2.x * p2.y + v3.x * p3.y;
        acc.y += v0.y * p0.y + v1.y * p1.y + v2.y * p2.y + v3.y * p3.y;
        acc.z += v0.z * p0.y + v1.z * p1.y + v2.z * p2.y + v3.z * p3.y;
        acc.w += v0.w * p0.y + v1.w * p1.y + v2.w * p2.y + v3.w * p3.y;
        ws += p0.y + p1.y + p2.y + p3.y;
        i += 4;
    }
    while (i < en) {
        float2 p = __ldg(&g_pack[i]);
        int s = __float_as_int(p.x);
        float4 v = *(const float4*)(x + (size_t)s * DIMV + c);
        acc.x += v.x * p.y; acc.y += v.y * p.y; acc.z += v.z * p.y; acc.w += v.w * p.y;
        ws += p.y;
        i++;
    }
    float inv = 1.0f / (ws + EPSV);
    *(float4*)&g_upd[(size_t)seg * DIMV + c] =
        make_float4(acc.x * inv, acc.y * inv, acc.z * inv, acc.w * inv);
}

// ---------------- hidden (tensor core): sigmoid([upd|x]@[lin;self] + b) ------
// Block: 64 nodes, 256 threads (8 warps). A [64][H_LDA] fp16 hi/lo,
// W^T [64][H_LDA] fp16 hi/lo. Smem total = 4*64*328*2 = 167936 B.
#define SMEM_H (4 * 64 * H_LDA * 2)

__global__ __launch_bounds__(256) void hidden_tc(
    const float* __restrict__ x_in,
    const float* __restrict__ lin_w, const float* __restrict__ lin_b,
    const float* __restrict__ self_w, const float* __restrict__ self_b,
    float* __restrict__ hid_out) {
    extern __shared__ __align__(16) __half smh[];
    __half* aHi = smh;
    __half* aLo = aHi + 64 * H_LDA;
    __half* wHi = aLo + 64 * H_LDA;
    __half* wLo = wHi + 64 * H_LDA;

    int tid = threadIdx.x;
    int node0 = blockIdx.x * 64;

    // stage A = [upd(256) | x(64)] rows, fp16 split
    for (int i = tid; i < 64 * 80; i += 256) {
        int row = i / 80;
        int c4 = (i % 80) * 4;
        int gn = node0 + row;
        float4 v = make_float4(0.f, 0.f, 0.f, 0.f);
        if (gn < NN_NODES) {
            if (c4 < 256) v = *(const float4*)&g_upd[(size_t)gn * 256 + c4];
            else          v = *(const float4*)&x_in[(size_t)gn * 64 + (c4 - 256)];
        }
        __half2 h0, l0, h1, l1;
        split2(v.x, v.y, h0, l0);
        split2(v.z, v.w, h1, l1);
        *(__half2*)&aHi[row * H_LDA + c4]     = h0;
        *(__half2*)&aHi[row * H_LDA + c4 + 2] = h1;
        *(__half2*)&aLo[row * H_LDA + c4]     = l0;
        *(__half2*)&aLo[row * H_LDA + c4 + 2] = l1;
    }

    // stage W^T (stacked lin_w then self_w), fp16 split
    for (int i = tid; i < H_K * 64; i += 256) {
        int k = i >> 6, j = i & 63;
        float f = (k < 256) ? __ldg(&lin_w[k * 64 + j]) : __ldg(&self_w[(k - 256) * 64 + j]);
        __half h = __float2half_rn(f);
        wHi[j * H_LDA + k] = h;
        wLo[j * H_LDA + k] = __float2half_rn(f - __half2float(h));
    }
    __syncthreads();

    int wid = tid >> 5, lane = tid & 31;
    int mr = (wid & 3) * 16;         // node strip
    int jb = (wid >> 2) * 32;        // output col base
    int r = lane >> 2, q = lane & 3;

    float acc[4][4];
#pragma unroll
    for (int a = 0; a < 4; a++)
#pragma unroll
        for (int b = 0; b < 4; b++) acc[a][b] = 0.f;

    const __half* aHp = aHi + (mr + r) * H_LDA + q * 2;
    const __half* aLp = aLo + (mr + r) * H_LDA + q * 2;

    for (int kb = 0; kb < H_K; kb += 16) {
        uint32_t ah[4], al[4];
        ah[0] = ldsm_u32(aHp + kb);
        ah[1] = ldsm_u32(aHp + kb + 8 * H_LDA);
        ah[2] = ldsm_u32(aHp + kb + 8);
        ah[3] = ldsm_u32(aHp + kb + 8 * H_LDA + 8);
        al[0] = ldsm_u32(aLp + kb);
        al[1] = ldsm_u32(aLp + kb + 8 * H_LDA);
        al[2] = ldsm_u32(aLp + kb + 8);
        al[3] = ldsm_u32(aLp + kb + 8 * H_LDA + 8);
#pragma unroll
        for (int nt = 0; nt < 4; nt++) {
            int j = jb + nt * 8 + r;
            uint32_t bh0 = ldsm_u32(&wHi[j * H_LDA + kb + q * 2]);
            uint32_t bh1 = ldsm_u32(&wHi[j * H_LDA + kb + q * 2 + 8]);
            uint32_t bl0 = ldsm_u32(&wLo[j * H_LDA + kb + q * 2]);
            uint32_t bl1 = ldsm_u32(&wLo[j * H_LDA + kb + q * 2 + 8]);
            mma_f16(acc[nt], ah, bh0, bh1);
            mma_f16(acc[nt], ah, bl0, bl1);
            mma_f16(acc[nt], al, bh0, bh1);
        }
    }

    int row0 = node0 + mr + r;
    int row1 = row0 + 8;
#pragma unroll
    for (int nt = 0; nt < 4; nt++) {
        int j = jb + nt * 8 + q * 2;
        float b0 = __ldg(&lin_b[j])     + __ldg(&self_b[j]);
        float b1 = __ldg(&lin_b[j + 1]) + __ldg(&self_b[j + 1]);
        if (row0 < NN_NODES) {
            float2 o = make_float2(sigf(acc[nt][0] + b0), sigf(acc[nt][1] + b1));
            *(float2*)&hid_out[(size_t)row0 * 64 + j] = o;
        }
        if (row1 < NN_NODES) {
            float2 o = make_float2(sigf(acc[nt][2] + b0), sigf(acc[nt][3] + b1));
            *(float2*)&hid_out[(size_t)row1 * 64 + j] = o;
        }
    }
}

// ---------------- highway (tensor core) --------------------------------------
// Block: 64 nodes, 256 threads. A = cat[hid|prev] [64][W_LDA] hi/lo,
// proj W^T + trans W^T [64][W_LDA] hi/lo each. Smem = 6*64*136*2 = 104448 B.
#define SMEM_W (6 * 64 * W_LDA * 2)

__global__ __launch_bounds__(256, 2) void highway_tc(
    const float* __restrict__ hid, const float* __restrict__ prev,
    const float* __restrict__ pw, const float* __restrict__ pb,
    const float* __restrict__ tw, const float* __restrict__ tb,
    float* __restrict__ out) {
    extern __shared__ __align__(16) __half smh[];
    __half* aHi = smh;
    __half* aLo = aHi + 64 * W_LDA;
    __half* pHi = aLo + 64 * W_LDA;
    __half* pLo = pHi + 64 * W_LDA;
    __half* tHi = pLo + 64 * W_LDA;
    __half* tLo = tHi + 64 * W_LDA;

    int tid = threadIdx.x;
    int node0 = blockIdx.x * 64;

    // stage cat = [hid(64) | prev(64)]
    for (int i = tid; i < 64 * 32; i += 256) {
        int row = i / 32;
        int c4 = (i % 32) * 4;
        int gn = node0 + row;
        float4 v = make_float4(0.f, 0.f, 0.f, 0.f);
        if (gn < NN_NODES) {
            if (c4 < 64) v = *(const float4*)&hid[(size_t)gn * 64 + c4];
            else         v = *(const float4*)&prev[(size_t)gn * 64 + (c4 - 64)];
        }
        __half2 h0, l0, h1, l1;
        split2(v.x, v.y, h0, l0);
        split2(v.z, v.w, h1, l1);
        *(__half2*)&aHi[row * W_LDA + c4]     = h0;
        *(__half2*)&aHi[row * W_LDA + c4 + 2] = h1;
        *(__half2*)&aLo[row * W_LDA + c4]     = l0;
        *(__half2*)&aLo[row * W_LDA + c4 + 2] = l1;
    }

    // stage W^T for proj and trans
    for (int i = tid; i < 128 * 64; i += 256) {
        int k = i >> 6, j = i & 63;
        float fp = __ldg(&pw[k * 64 + j]);
        float ft = __ldg(&tw[k * 64 + j]);
        __half hp = __float2half_rn(fp);
        __half ht = __float2half_rn(ft);
        pHi[j * W_LDA + k] = hp;
        pLo[j * W_LDA + k] = __float2half_rn(fp - __half2float(hp));
        tHi[j * W_LDA + k] = ht;
        tLo[j * W_LDA + k] = __float2half_rn(ft - __half2float(ht));
    }
    __syncthreads();

    int wid = tid >> 5, lane = tid & 31;
    int mr = (wid & 3) * 16;
    int jb = (wid >> 2) * 32;
    int r = lane >> 2, q = lane & 3;

    float accp[4][4], acct[4][4];
#pragma unroll
    for (int a = 0; a < 4; a++)
#pragma unroll
        for (int b = 0; b < 4; b++) { accp[a][b] = 0.f; acct[a][b] = 0.f; }

    const __half* aHp = aHi + (mr + r) * W_LDA + q * 2;
    const __half* aLp = aLo + (mr + r) * W_LDA + q * 2;

    for (int kb = 0; kb < 128; kb += 16) {
        uint32_t ah[4], al[4];
        ah[0] = ldsm_u32(aHp + kb);
        ah[1] = ldsm_u32(aHp + kb + 8 * W_LDA);
        ah[2] = ldsm_u32(aHp + kb + 8);
        ah[3] = ldsm_u32(aHp + kb + 8 * W_LDA + 8);
        al[0] = ldsm_u32(aLp + kb);
        al[1] = ldsm_u32(aLp + kb + 8 * W_LDA);
        al[2] = ldsm_u32(aLp + kb + 8);
        al[3] = ldsm_u32(aLp + kb + 8 * W_LDA + 8);
#pragma unroll
        for (int nt = 0; nt < 4; nt++) {
            int j = jb + nt * 8 + r;
            int base = j * W_LDA + kb + q * 2;
            uint32_t ph0 = ldsm_u32(&pHi[base]);
            uint32_t ph1 = ldsm_u32(&pHi[base + 8]);
            uint32_t pl0 = ldsm_u32(&pLo[base]);
            uint32_t pl1 = ldsm_u32(&pLo[base + 8]);
            mma_f16(accp[nt], ah, ph0, ph1);
            mma_f16(accp[nt], ah, pl0, pl1);
            mma_f16(accp[nt], al, ph0, ph1);
            uint32_t th0 = ldsm_u32(&tHi[base]);
            uint32_t th1 = ldsm_u32(&tHi[base + 8]);
            uint32_t tl0 = ldsm_u32(&tLo[base]);
            uint32_t tl1 = ldsm_u32(&tLo[base + 8]);
            mma_f16(acct[nt], ah, th0, th1);
            mma_f16(acct[nt], ah, tl0, tl1);
            mma_f16(acct[nt], al, th0, th1);
        }
    }

    int row0 = node0 + mr + r;
    int row1 = row0 + 8;
#pragma unroll
    for (int nt = 0; nt < 4; nt++) {
        int j = jb + nt * 8 + q * 2;
        float pb0 = __ldg(&pb[j]), pb1 = __ldg(&pb[j + 1]);
        float tb0 = __ldg(&tb[j]), tb1 = __ldg(&tb[j + 1]);
        if (row0 < NN_NODES) {
            float2 h = *(const float2*)&hid[(size_t)row0 * 64 + j];
            float p0 = fmaxf(accp[nt][0] + pb0, 0.f);
            float p1 = fmaxf(accp[nt][1] + pb1, 0.f);
            float g0 = sigf(acct[nt][0] + tb0);
            float g1 = sigf(acct[nt][1] + tb1);
            float2 o = make_float2(g0 * p0 + (1.f - g0) * h.x,
                                   g1 * p1 + (1.f - g1) * h.y);
            *(float2*)&out[(size_t)row0 * 64 + j] = o;
        }
        if (row1 < NN_NODES) {
            float2 h = *(const float2*)&hid[(size_t)row1 * 64 + j];
            float p0 = fmaxf(accp[nt][2] + pb0, 0.f);
            float p1 = fmaxf(accp[nt][3] + pb1, 0.f);
            float g0 = sigf(acct[nt][2] + tb0);
            float g1 = sigf(acct[nt][3] + tb1);
            float2 o = make_float2(g0 * p0 + (1.f - g0) * h.x,
                                   g1 * p1 + (1.f - g1) * h.y);
            *(float2*)&out[(size_t)row1 * 64 + j] = o;
        }
    }
}

// ---------------- host ----------------
extern "C" void kernel_launch(void* const* d_in, const int* in_sizes, int n_in,
                              void* d_out, int out_size) {
    const float* node_feat   = (const float*)d_in[0];
    const float* ew          = (const float*)d_in[1];
    const float* conv_lin_w  = (const float*)d_in[2];
    const float* conv_lin_b  = (const float*)d_in[3];
    const float* conv_self_w = (const float*)d_in[4];
    const float* conv_self_b = (const float*)d_in[5];
    const float* hw_proj_w   = (const float*)d_in[6];
    const float* hw_proj_b   = (const float*)d_in[7];
    const float* hw_trans_w  = (const float*)d_in[8];
    const float* hw_trans_b  = (const float*)d_in[9];
    const int*   src         = (const int*)d_in[10];
    const int*   dst         = (const int*)d_in[11];
    const int*   rel         = (const int*)d_in[12];
    float* out = (float*)d_out;

    void* buf_p = nullptr;
    cudaGetSymbolAddress(&buf_p, g_buf);
    float* hid0  = (float*)buf_p;
    float* hid1  = hid0 + (size_t)NN_NODES * DIMV;
    float* gated = hid1 + (size_t)NN_NODES * DIMV;
    float* hidv[2] = {hid0, hid1};

    cudaFuncSetAttribute(hidden_tc, cudaFuncAttributeMaxDynamicSharedMemorySize, SMEM_H);
    cudaFuncSetAttribute(highway_tc, cudaFuncAttributeMaxDynamicSharedMemorySize, SMEM_W);

    // ---- CSR build (graph static across layers) ----
    zero_kernel<<<(NSEG + 255) / 256, 256>>>();
    hist_kernel<<<(NN_EDGES + 255) / 256, 256>>>(dst, rel);
    scanA_kernel<<<NB1, 1024>>>();
    scanB_kernel<<<1, 256>>>();
    fill_kernel<<<(NN_EDGES + 255) / 256, 256>>>(ew, src, dst, rel);

    const float* x = node_feat;
    const float* prev = node_feat;
    int nblk = (NN_NODES + 63) / 64;

    for (int L = 0; L < 3; L++) {
        gather_kernel<<<(int)(((size_t)NSEG * 16 + 255) / 256), 256>>>(x);

        float* hid = hidv[L & 1];
        hidden_tc<<<nblk, 256, SMEM_H>>>(
            x,
            conv_lin_w + (size_t)L * 256 * 64, conv_lin_b + L * 64,
            conv_self_w + (size_t)L * 64 * 64, conv_self_b + L * 64,
            hid);

        float* o = (L == 2) ? out : gated;
        highway_tc<<<nblk, 256, SMEM_W>>>(
            hid, prev,
            hw_proj_w + (size_t)L * 128 * 64, hw_proj_b + L * 64,
            hw_trans_w + (size_t)L * 128 * 64, hw_trans_b + L * 64,
            o);

        x = o;
        prev = hid;
    }
}